// round 4
// baseline (speedup 1.0000x reference)
#include <cuda_runtime.h>

// ---------------------------------------------------------------------------
// GCN 2-layer: out = GCN(relu(GCN(x, W1, b1)), W2, b2)
// Strategy:
//   deg count (int atomics) -> single-block scan -> CSR fill (cursor atomics)
//   gemm1: h1s = (x@W1) * dinv[row]      (scaled rows)
//   agg1 (gather, warp/node): fm = relu(dinv*(2*h1s[self] + sum h1s[src]) + b1)
//   gemm2: h2s = (fm@W2) * dinv[row]
//   agg2: out = dinv*(2*h2s[self] + sum h2s[src]) + b2
// ---------------------------------------------------------------------------

#define MAXN 100000
#define MAXE 2000000

__device__ int   g_cnt[MAXN];
__device__ int   g_rowstart[MAXN + 1];
__device__ int   g_cursor[MAXN];
__device__ float g_dinv[MAXN];
__device__ int   g_csr[MAXE];
__device__ float g_h1s[(size_t)MAXN * 64];
__device__ float g_h2s[(size_t)MAXN * 32];
__device__ int   g_is64;

// Detect whether edge_index is int64 (all odd 32-bit words zero since values
// are < 2^31) or int32. Samples 64 odd positions spread across the buffer.
__global__ void k_detect(const int* __restrict__ p) {
    int o = 0;
#pragma unroll
    for (int i = 0; i < 64; i++) o |= p[2 * i * 25000 + 1];
    g_is64 = (o == 0) ? 1 : 0;
}

__global__ void k_zero(int n) {
    int i = blockIdx.x * blockDim.x + threadIdx.x;
    if (i < n) g_cnt[i] = 0;
}

__device__ __forceinline__ int2 load_edge(const void* idx, int E, int e) {
    if (g_is64) {
        const long long* p = (const long long*)idx;
        return make_int2((int)p[e], (int)p[E + e]);
    } else {
        const int* p = (const int*)idx;
        return make_int2(p[e], p[E + e]);
    }
}

__global__ void k_count(const void* __restrict__ idx, int E) {
    int e = blockIdx.x * blockDim.x + threadIdx.x;
    if (e >= E) return;
    int2 sd = load_edge(idx, E, e);
    atomicAdd(&g_cnt[sd.y], 1);
}

// Single-block exclusive scan over degree counts; also computes dinv and
// initializes the fill cursors.
__global__ void k_scan(int n) {
    __shared__ int part[1024];
    int tid = threadIdx.x;
    int chunk = (n + 1023) / 1024;
    int b = tid * chunk;
    int e = min(b + chunk, n);
    int s = 0;
    for (int i = b; i < e; i++) s += g_cnt[i];
    part[tid] = s;
    __syncthreads();
    for (int off = 1; off < 1024; off <<= 1) {
        int v = (tid >= off) ? part[tid - off] : 0;
        __syncthreads();
        part[tid] += v;
        __syncthreads();
    }
    int offset = (tid > 0) ? part[tid - 1] : 0;
    for (int i = b; i < e; i++) {
        int c = g_cnt[i];
        g_rowstart[i] = offset;
        g_cursor[i] = offset;
        g_dinv[i] = rsqrtf((float)c + 2.0f);  // improved self-loops: +2.0
        offset += c;
    }
    if (tid == 0) g_rowstart[n] = part[1023];
}

__global__ void k_fill(const void* __restrict__ idx, int E) {
    int e = blockIdx.x * blockDim.x + threadIdx.x;
    if (e >= E) return;
    int2 sd = load_edge(idx, E, e);
    int p = atomicAdd(&g_cursor[sd.y], 1);
    g_csr[p] = sd.x;
}

// out[row][:] = (X[row][:] @ W) * dinv[row].  FIN = 64 fixed.
template <int FOUT>
__global__ void k_gemm_scale(const float* __restrict__ X,
                             const float* __restrict__ W,
                             float* __restrict__ out, int rows) {
    __shared__ float Ws[64 * FOUT];
    for (int i = threadIdx.x; i < 64 * FOUT; i += blockDim.x) Ws[i] = W[i];
    __syncthreads();
    int row = blockIdx.x * blockDim.x + threadIdx.x;
    if (row >= rows) return;

    float4 xr[16];
    const float4* xp = (const float4*)(X + (size_t)row * 64);
#pragma unroll
    for (int i = 0; i < 16; i++) xr[i] = xp[i];
    const float* xs = (const float*)xr;

    float acc[FOUT];
#pragma unroll
    for (int j = 0; j < FOUT; j++) acc[j] = 0.0f;

#pragma unroll
    for (int k = 0; k < 64; k++) {
        float xv = xs[k];
#pragma unroll
        for (int j = 0; j < FOUT; j++) acc[j] += xv * Ws[k * FOUT + j];
    }

    float w = g_dinv[row];
    float* o = out + (size_t)row * FOUT;
#pragma unroll
    for (int j = 0; j < FOUT; j += 4) {
        float4 v = make_float4(acc[j] * w, acc[j + 1] * w, acc[j + 2] * w,
                               acc[j + 3] * w);
        *(float4*)(o + j) = v;
    }
}

// Gather-aggregate: one warp per node. CPL = F/32 columns per lane.
template <int F, bool RELU>
__global__ void k_agg(const float* __restrict__ hs,
                      const float* __restrict__ bias,
                      float* __restrict__ out, int n) {
    int gtid = blockIdx.x * blockDim.x + threadIdx.x;
    int node = gtid >> 5;
    int lane = gtid & 31;
    if (node >= n) return;

    const int CPL = F / 32;
    int col = lane * CPL;

    float acc0, acc1 = 0.0f;
    if (CPL == 2) {
        float2 sv = *(const float2*)(hs + (size_t)node * F + col);
        acc0 = 2.0f * sv.x;
        acc1 = 2.0f * sv.y;
    } else {
        acc0 = 2.0f * hs[(size_t)node * F + col];
    }

    int s = g_rowstart[node];
    int e = g_rowstart[node + 1];
    for (int j = s; j < e; j++) {
        int src = g_csr[j];
        if (CPL == 2) {
            float2 v = *(const float2*)(hs + (size_t)src * F + col);
            acc0 += v.x;
            acc1 += v.y;
        } else {
            acc0 += hs[(size_t)src * F + col];
        }
    }

    float w = g_dinv[node];
    if (CPL == 2) {
        float r0 = acc0 * w + bias[col];
        float r1 = acc1 * w + bias[col + 1];
        if (RELU) {
            r0 = fmaxf(r0, 0.0f);
            r1 = fmaxf(r1, 0.0f);
        }
        *(float2*)(out + (size_t)node * F + col) = make_float2(r0, r1);
    } else {
        float r0 = acc0 * w + bias[col];
        if (RELU) r0 = fmaxf(r0, 0.0f);
        out[(size_t)node * F + col] = r0;
    }
}

extern "C" void kernel_launch(void* const* d_in, const int* in_sizes, int n_in,
                              void* d_out, int out_size) {
    const float* x   = (const float*)d_in[0];
    const void*  idx = d_in[1];
    const float* W1  = (const float*)d_in[2];
    const float* b1  = (const float*)d_in[3];
    const float* W2  = (const float*)d_in[4];
    const float* b2  = (const float*)d_in[5];

    int N = in_sizes[0] / 64;       // 100000
    int E = in_sizes[1] / 2;        // 1600000 (element count same for i32/i64)

    float* out = (float*)d_out;                 // [N, 32]
    float* fm  = out + (size_t)N * 32;          // [N, 64] feature_map

    // graph build
    k_detect<<<1, 1>>>((const int*)idx);
    k_zero<<<(N + 255) / 256, 256>>>(N);
    k_count<<<(E + 255) / 256, 256>>>(idx, E);
    k_scan<<<1, 1024>>>(N);
    k_fill<<<(E + 255) / 256, 256>>>(idx, E);

    // layer 1
    k_gemm_scale<64><<<(N + 255) / 256, 256>>>(x, W1, g_h1s, N);
    int aggBlocks = (N * 32 + 255) / 256;
    k_agg<64, true><<<aggBlocks, 256>>>(g_h1s, b1, fm, N);

    // layer 2
    k_gemm_scale<32><<<(N + 255) / 256, 256>>>(fm, W2, g_h2s, N);
    k_agg<32, false><<<aggBlocks, 256>>>(g_h2s, b2, out, N);
}

// round 5
// speedup vs baseline: 1.5680x; 1.5680x over previous
#include <cuda_runtime.h>

// ---------------------------------------------------------------------------
// GCN 2-layer: out = GCN(relu(GCN(x, W1, b1)), W2, b2)
//   graph build: count -> 3-phase parallel scan -> CSR fill
//   gemm (tiled, 4x4 micro): h1s = (x@W1) * dinv[row]
//   agg (gather, warp/node, 4x unrolled): fm = relu(dinv*(2*self + sum) + b)
// ---------------------------------------------------------------------------

#define MAXN 100000
#define MAXE 2000000
#define SCAN_BLK 1024

__device__ int   g_cnt[MAXN];
__device__ int   g_rowstart[MAXN + 1];
__device__ int   g_cursor[MAXN];
__device__ float g_dinv[MAXN];
__device__ int   g_csr[MAXE];
__device__ float g_h1s[(size_t)MAXN * 64];
__device__ float g_h2s[(size_t)MAXN * 32];
__device__ int   g_is64;
__device__ int   g_bsum[256];
__device__ int   g_bpre[256];

// int64 vs int32 detection: all node ids < 2^31, so int64 => odd words zero.
__global__ void k_detect(const int* __restrict__ p) {
    int o = 0;
#pragma unroll
    for (int i = 0; i < 64; i++) o |= p[2 * i * 25000 + 1];
    g_is64 = (o == 0) ? 1 : 0;
}

__global__ void k_zero(int n) {
    int i = blockIdx.x * blockDim.x + threadIdx.x;
    if (i < n) g_cnt[i] = 0;
}

__device__ __forceinline__ int2 load_edge(const void* idx, int E, int e) {
    if (g_is64) {
        const long long* p = (const long long*)idx;
        return make_int2((int)p[e], (int)p[E + e]);
    } else {
        const int* p = (const int*)idx;
        return make_int2(p[e], p[E + e]);
    }
}

__global__ void k_count(const void* __restrict__ idx, int E) {
    int e = blockIdx.x * blockDim.x + threadIdx.x;
    if (e >= E) return;
    int2 sd = load_edge(idx, E, e);
    atomicAdd(&g_cnt[sd.y], 1);
}

// ---- 3-phase parallel scan over degree counts ----
__global__ void k_bsum(int n) {
    __shared__ int red[256];
    int base = blockIdx.x * SCAN_BLK;
    int s = 0;
    for (int i = threadIdx.x; i < SCAN_BLK; i += 256) {
        int idx = base + i;
        if (idx < n) s += g_cnt[idx];
    }
    red[threadIdx.x] = s;
    __syncthreads();
    for (int o = 128; o > 0; o >>= 1) {
        if (threadIdx.x < o) red[threadIdx.x] += red[threadIdx.x + o];
        __syncthreads();
    }
    if (threadIdx.x == 0) g_bsum[blockIdx.x] = red[0];
}

__global__ void k_bscan(int nb) {  // blockDim = 256, nb <= 256
    __shared__ int sh[256];
    int t = threadIdx.x;
    int v = (t < nb) ? g_bsum[t] : 0;
    sh[t] = v;
    __syncthreads();
    for (int o = 1; o < 256; o <<= 1) {
        int u = (t >= o) ? sh[t - o] : 0;
        __syncthreads();
        sh[t] += u;
        __syncthreads();
    }
    if (t < nb) g_bpre[t] = sh[t] - v;  // exclusive
}

__global__ void k_prefix(int n) {
    __shared__ int tsum[256];
    int base = blockIdx.x * SCAN_BLK;
    int t = threadIdx.x;
    int idx0 = base + t * 4;
    int c[4], local[4];
    int s = 0;
#pragma unroll
    for (int i = 0; i < 4; i++) {
        int idx = idx0 + i;
        c[i] = (idx < n) ? g_cnt[idx] : 0;
        local[i] = s;
        s += c[i];
    }
    tsum[t] = s;
    __syncthreads();
    for (int o = 1; o < 256; o <<= 1) {
        int u = (t >= o) ? tsum[t - o] : 0;
        __syncthreads();
        tsum[t] += u;
        __syncthreads();
    }
    int off = g_bpre[blockIdx.x] + (tsum[t] - s);
#pragma unroll
    for (int i = 0; i < 4; i++) {
        int idx = idx0 + i;
        if (idx < n) {
            int rs = off + local[i];
            g_rowstart[idx] = rs;
            g_cursor[idx] = rs;
            g_dinv[idx] = rsqrtf((float)c[i] + 2.0f);  // improved self-loops
        }
    }
    if (base + SCAN_BLK >= n && t == 255) g_rowstart[n] = off + s;
}

__global__ void k_fill(const void* __restrict__ idx, int E) {
    int e = blockIdx.x * blockDim.x + threadIdx.x;
    if (e >= E) return;
    int2 sd = load_edge(idx, E, e);
    int p = atomicAdd(&g_cursor[sd.y], 1);
    g_csr[p] = sd.x;
}

// ---- tiled GEMM with dinv row-scaling: out[r][:] = (X[r][:] @ W) * dinv[r]
// 256 threads, 4x4 micro-tile. BN = FOUT (block spans full output width).
template <int BM, int BN>
__global__ void k_gemm(const float* __restrict__ X, const float* __restrict__ W,
                       float* __restrict__ out, int rows) {
    constexpr int TX = BN / 4;          // threads along columns
    __shared__ float XsT[64][BM + 4];   // transposed X tile: [k][row]
    __shared__ float Ws[64][BN];        // [k][col]
    int tid = threadIdx.x;
    int row0 = blockIdx.x * BM;

    // load W (64*BN floats) via float4
    for (int i = tid; i < 64 * BN / 4; i += 256)
        ((float4*)&Ws[0][0])[i] = ((const float4*)W)[i];

    // load X tile transposed; zero-pad out-of-range rows
    for (int i = tid; i < BM * 16; i += 256) {
        int r = i / 16, q = i % 16;
        float4 v = make_float4(0.f, 0.f, 0.f, 0.f);
        int gr = row0 + r;
        if (gr < rows) v = ((const float4*)(X + (size_t)gr * 64))[q];
        XsT[q * 4 + 0][r] = v.x;
        XsT[q * 4 + 1][r] = v.y;
        XsT[q * 4 + 2][r] = v.z;
        XsT[q * 4 + 3][r] = v.w;
    }
    __syncthreads();

    int tx = tid % TX, ty = tid / TX;
    int ci = tx * 4, ri = ty * 4;
    float acc[4][4] = {};

#pragma unroll
    for (int k = 0; k < 64; k++) {
        float4 xv = *(const float4*)&XsT[k][ri];
        float4 wv = *(const float4*)&Ws[k][ci];
        acc[0][0] += xv.x * wv.x; acc[0][1] += xv.x * wv.y;
        acc[0][2] += xv.x * wv.z; acc[0][3] += xv.x * wv.w;
        acc[1][0] += xv.y * wv.x; acc[1][1] += xv.y * wv.y;
        acc[1][2] += xv.y * wv.z; acc[1][3] += xv.y * wv.w;
        acc[2][0] += xv.z * wv.x; acc[2][1] += xv.z * wv.y;
        acc[2][2] += xv.z * wv.z; acc[2][3] += xv.z * wv.w;
        acc[3][0] += xv.w * wv.x; acc[3][1] += xv.w * wv.y;
        acc[3][2] += xv.w * wv.z; acc[3][3] += xv.w * wv.w;
    }

#pragma unroll
    for (int i = 0; i < 4; i++) {
        int gr = row0 + ri + i;
        if (gr < rows) {
            float w = g_dinv[gr];
            float4 v = make_float4(acc[i][0] * w, acc[i][1] * w,
                                   acc[i][2] * w, acc[i][3] * w);
            *(float4*)(out + (size_t)gr * BN + ci) = v;
        }
    }
}

// ---- gather-aggregate: one warp per node, 4x unrolled for MLP ----
template <int F, bool RELU>
__global__ void k_agg(const float* __restrict__ hs,
                      const float* __restrict__ bias,
                      float* __restrict__ out, int n) {
    int gtid = blockIdx.x * blockDim.x + threadIdx.x;
    int node = gtid >> 5;
    int lane = gtid & 31;
    if (node >= n) return;

    const int CPL = F / 32;
    int col = lane * CPL;

    float acc0, acc1 = 0.0f;
    if (CPL == 2) {
        float2 sv = *(const float2*)(hs + (size_t)node * F + col);
        acc0 = 2.0f * sv.x;
        acc1 = 2.0f * sv.y;
    } else {
        acc0 = 2.0f * hs[(size_t)node * F + col];
    }

    int s = g_rowstart[node];
    int e = g_rowstart[node + 1];
    int j = s;
    for (; j + 4 <= e; j += 4) {
        int s0 = g_csr[j], s1 = g_csr[j + 1], s2 = g_csr[j + 2], s3 = g_csr[j + 3];
        if (CPL == 2) {
            float2 v0 = *(const float2*)(hs + (size_t)s0 * F + col);
            float2 v1 = *(const float2*)(hs + (size_t)s1 * F + col);
            float2 v2 = *(const float2*)(hs + (size_t)s2 * F + col);
            float2 v3 = *(const float2*)(hs + (size_t)s3 * F + col);
            acc0 += v0.x + v1.x + v2.x + v3.x;
            acc1 += v0.y + v1.y + v2.y + v3.y;
        } else {
            float v0 = hs[(size_t)s0 * F + col];
            float v1 = hs[(size_t)s1 * F + col];
            float v2 = hs[(size_t)s2 * F + col];
            float v3 = hs[(size_t)s3 * F + col];
            acc0 += v0 + v1 + v2 + v3;
        }
    }
    for (; j < e; j++) {
        int src = g_csr[j];
        if (CPL == 2) {
            float2 v = *(const float2*)(hs + (size_t)src * F + col);
            acc0 += v.x;
            acc1 += v.y;
        } else {
            acc0 += hs[(size_t)src * F + col];
        }
    }

    float w = g_dinv[node];
    if (CPL == 2) {
        float r0 = acc0 * w + bias[col];
        float r1 = acc1 * w + bias[col + 1];
        if (RELU) {
            r0 = fmaxf(r0, 0.0f);
            r1 = fmaxf(r1, 0.0f);
        }
        *(float2*)(out + (size_t)node * F + col) = make_float2(r0, r1);
    } else {
        float r0 = acc0 * w + bias[col];
        if (RELU) r0 = fmaxf(r0, 0.0f);
        out[(size_t)node * F + col] = r0;
    }
}

extern "C" void kernel_launch(void* const* d_in, const int* in_sizes, int n_in,
                              void* d_out, int out_size) {
    const float* x   = (const float*)d_in[0];
    const void*  idx = d_in[1];
    const float* W1  = (const float*)d_in[2];
    const float* b1  = (const float*)d_in[3];
    const float* W2  = (const float*)d_in[4];
    const float* b2  = (const float*)d_in[5];

    int N = in_sizes[0] / 64;   // 100000
    int E = in_sizes[1] / 2;    // 1600000

    float* out = (float*)d_out;            // [N, 32]
    float* fm  = out + (size_t)N * 32;     // [N, 64] feature_map

    int nb = (N + SCAN_BLK - 1) / SCAN_BLK;

    // graph build
    k_detect<<<1, 1>>>((const int*)idx);
    k_zero<<<(N + 255) / 256, 256>>>(N);
    k_count<<<(E + 255) / 256, 256>>>(idx, E);
    k_bsum<<<nb, 256>>>(N);
    k_bscan<<<1, 256>>>(nb);
    k_prefix<<<nb, 256>>>(N);
    k_fill<<<(E + 255) / 256, 256>>>(idx, E);

    // layer 1: 64 -> 64
    k_gemm<64, 64><<<(N + 63) / 64, 256>>>(x, W1, g_h1s, N);
    int aggBlocks = (N * 32 + 255) / 256;
    k_agg<64, true><<<aggBlocks, 256>>>(g_h1s, b1, fm, N);

    // layer 2: 64 -> 32
    k_gemm<128, 32><<<(N + 127) / 128, 256>>>(fm, W2, g_h2s, N);
    k_agg<32, false><<<aggBlocks, 256>>>(g_h2s, b2, out, N);
}